// round 2
// baseline (speedup 1.0000x reference)
#include <cuda_runtime.h>
#include <math.h>

// ---------------------------------------------------------------------------
// SimpleVQ: B=32, H=1, L=4096, D=64, S=512
// Outputs (concatenated f32): quantized[NVEC*64] | z[NVEC] | l_commit | errs2[NVEC]
// ---------------------------------------------------------------------------

typedef unsigned long long ull;

#define NVEC   131072
#define DIMD   64
#define NCODE  512
#define ZOFF   8388608           // NVEC*DIMD
#define LOFF   8519680           // ZOFF + NVEC
#define EOFF   8519681
#define NBLK   148               // persistent grid (1 block/SM on sm_100a)
#define NTHR   512
#define VSTRIDE (NBLK * NTHR)    // 75776
#define SMEM_BYTES (131072 + 2048 + 2048)  // codebook(128KB) + cn(2KB) + reduce(2KB)

// Codebook, dim-pair-packed ull layout:
//   g_cb[((s>>3)*32 + j)*8 + (s&7)] = pack( c[s][2j], c[s][2j+1] )
__device__ ull   g_cb[NCODE * 32];
__device__ float g_cn[NCODE];
__device__ float g_part[NBLK];

// ---- packed f32x2 helpers (Blackwell) -------------------------------------
__device__ __forceinline__ void unpack2(ull v, float &x, float &y) {
    asm("mov.b64 {%0, %1}, %2;" : "=f"(x), "=f"(y) : "l"(v));
}
__device__ __forceinline__ void ffma2(ull &acc, ull a, ull b) {
    asm("fma.rn.f32x2 %0, %1, %2, %0;" : "+l"(acc) : "l"(a), "l"(b));
}

// ---------------------------------------------------------------------------
// Init: 512 blocks (one per codeword) x 64 threads (one per dim).
// Same math as the passing R1 version (double trig, fp32 pre-mul).
// ---------------------------------------------------------------------------
__global__ void vq_init() {
    __shared__ float red[64];
    const int s = blockIdx.x;
    const int d = threadIdx.x;
    const int j = d & 31;

    double expn = -((double)(2 * j) / 64.0);
    float  il   = (float)pow(100000.0, expn);
    float  pre  = __fmul_rn((float)s, il);
    float  e    = (d < 32) ? (float)sin((double)pre) : (float)cos((double)pre);

    // reduce sum of squares over 64 threads (fixed-shape tree)
    red[d] = __fmul_rn(e, e);
    __syncthreads();
    for (int o = 32; o > 0; o >>= 1) {
        if (d < o) red[d] = __fadd_rn(red[d], red[d + o]);
        __syncthreads();
    }
    float m = __fadd_rn(__fmul_rn(red[0], (1.0f / 64.0f)), 1e-6f);
    __syncthreads();
    float r = (float)(1.0 / sqrt((double)m));

    float c = __fmul_rn(__fmul_rn(e, r), 0.35355339059327373f);  // * 64^-0.25

    // store into packed layout
    float* cbf = (float*)g_cb;
    cbf[(((s >> 3) * 32 + (d >> 1)) * 8 + (s & 7)) * 2 + (d & 1)] = c;

    // ||c||^2 via same tree
    red[d] = __fmul_rn(c, c);
    __syncthreads();
    for (int o = 32; o > 0; o >>= 1) {
        if (d < o) red[d] = __fadd_rn(red[d], red[d + o]);
        __syncthreads();
    }
    if (d == 0) g_cn[s] = red[0];
}

// ---------------------------------------------------------------------------
// Main: persistent 148 blocks x 512 threads, 1 vector per thread per round.
// Codebook in smem. Inner loop: 8 codes/group, lanes = (even dim, odd dim),
// so the vector ull is used directly as FFMA2 operand (no packing).
// ---------------------------------------------------------------------------
__global__ void __launch_bounds__(NTHR) vq_main(const float* __restrict__ vecs,
                                                const float* __restrict__ mask,
                                                float* __restrict__ out) {
    extern __shared__ unsigned char smem[];
    ull*   scb  = (ull*)smem;                       // 512*32 ulls = 128KB
    float* scn  = (float*)(smem + 131072);          // 512 floats
    float* sred = scn + NCODE;                      // 512 floats

    const int t = threadIdx.x;
    {
        ulonglong2*       d2 = (ulonglong2*)scb;
        const ulonglong2* s2 = (const ulonglong2*)g_cb;
        for (int i = t; i < (NCODE * 32) / 2; i += NTHR) d2[i] = s2[i];
        if (t < NCODE) scn[t] = g_cn[t];
    }
    __syncthreads();

    float lacc = 0.f;

    for (int v = blockIdx.x * NTHR + t; v < NVEC; v += VSTRIDE) {
        // load vector as 32 packed (even,odd) ulls
        ull va[32];
        {
            const ulonglong2* pv = (const ulonglong2*)(vecs + (size_t)v * DIMD);
#pragma unroll
            for (int i = 0; i < 16; i++) {
                ulonglong2 x = pv[i];
                va[2 * i] = x.x; va[2 * i + 1] = x.y;
            }
        }
        // ||v||^2 (lane-split then add)
        ull an = 0ull;
#pragma unroll
        for (int j = 0; j < 32; j++) ffma2(an, va[j], va[j]);
        float nlo, nhi; unpack2(an, nlo, nhi);
        const float vn = __fadd_rn(nlo, nhi);

        float best = 3.4e38f;
        int   bi   = 0;

#pragma unroll 1
        for (int g = 0; g < NCODE / 8; g++) {
            const ulonglong2* cb2 = (const ulonglong2*)(scb + g * 256);
            ull a0 = 0ull, a1 = 0ull, a2 = 0ull, a3 = 0ull;
            ull a4 = 0ull, a5 = 0ull, a6 = 0ull, a7 = 0ull;
#pragma unroll
            for (int j = 0; j < 32; j++) {
                ulonglong2 c01 = cb2[j * 4 + 0];
                ulonglong2 c23 = cb2[j * 4 + 1];
                ulonglong2 c45 = cb2[j * 4 + 2];
                ulonglong2 c67 = cb2[j * 4 + 3];
                ull w = va[j];
                ffma2(a0, w, c01.x); ffma2(a1, w, c01.y);
                ffma2(a2, w, c23.x); ffma2(a3, w, c23.y);
                ffma2(a4, w, c45.x); ffma2(a5, w, c45.y);
                ffma2(a6, w, c67.x); ffma2(a7, w, c67.y);
            }
            const int s0 = g * 8;
            ull accs[8] = {a0, a1, a2, a3, a4, a5, a6, a7};
#pragma unroll
            for (int k = 0; k < 8; k++) {
                float lo, hi; unpack2(accs[k], lo, hi);
                float dot = __fadd_rn(lo, hi);
                float dst = __fadd_rn(fmaf(-2.f, dot, vn), scn[s0 + k]);
                if (dst < best) { best = dst; bi = s0 + k; }  // first-min wins
            }
        }

        // quantized = codebook[bi]  (STE terms cancel exactly)
        {
            const ull* crow = scb + (bi >> 3) * 256 + (bi & 7);
            float2* q = (float2*)(out + (size_t)v * DIMD);
#pragma unroll
            for (int j = 0; j < 32; j++) {
                float lo, hi; unpack2(crow[j * 8], lo, hi);
                float2 w; w.x = lo; w.y = hi;
                q[j] = w;
            }
        }

        out[ZOFF + v] = (float)bi;
        float er = fmaxf(best, 0.f);
        out[EOFF + v] = er;
        lacc = __fadd_rn(lacc, __fmul_rn(mask[v], er));
    }

    // deterministic block partial for l_commit (static work assignment)
    sred[t] = lacc;
    __syncthreads();
    for (int o = NTHR / 2; o > 0; o >>= 1) {
        if (t < o) sred[t] = __fadd_rn(sred[t], sred[t + o]);
        __syncthreads();
    }
    if (t == 0) g_part[blockIdx.x] = sred[0];
}

// ---------------------------------------------------------------------------
// Final: deterministic fixed-order reduction of 148 partials -> l_commit
// ---------------------------------------------------------------------------
__global__ void vq_final(float* __restrict__ out) {
    __shared__ float s[256];
    int t = threadIdx.x;
    s[t] = (t < NBLK) ? g_part[t] : 0.f;
    __syncthreads();
    for (int o = 128; o > 0; o >>= 1) {
        if (t < o) s[t] = __fadd_rn(s[t], s[t + o]);
        __syncthreads();
    }
    if (t == 0) out[LOFF] = __fmul_rn(s[0], (1.0f / 131072.0f));
}

// ---------------------------------------------------------------------------
extern "C" void kernel_launch(void* const* d_in, const int* in_sizes, int n_in,
                              void* d_out, int out_size) {
    (void)in_sizes; (void)n_in; (void)out_size;
    const float* vecs = (const float*)d_in[0];   // [32,1,4096,64] f32
    const float* mask = (const float*)d_in[1];   // [32,4096] f32
    float* out = (float*)d_out;

    cudaFuncSetAttribute(vq_main, cudaFuncAttributeMaxDynamicSharedMemorySize, SMEM_BYTES);

    vq_init<<<NCODE, 64>>>();
    vq_main<<<NBLK, NTHR, SMEM_BYTES>>>(vecs, mask, out);
    vq_final<<<1, 256>>>(out);
}

// round 5
// speedup vs baseline: 1.1483x; 1.1483x over previous
#include <cuda_runtime.h>
#include <cuda_bf16.h>
#include <math.h>
#include <stdint.h>

// ---------------------------------------------------------------------------
// SimpleVQ: B=32, H=1, L=4096, D=64, S=512
// out (f32): quantized[NVEC*64] | z[NVEC] | l_commit | errs2[NVEC]
// HMMA (mma.sync bf16, fragments built by construction, codebook-in-registers)
// + bf16 distance buffer + margin-certified exact fp32 refine.
// ---------------------------------------------------------------------------

typedef unsigned long long ull;

#define NVEC   131072
#define NCODE  512
#define ZOFF   8388608
#define LOFF   8519680
#define EOFF   8519681
#define NBLK   148
#define NTHR   512
#define NTILE  1024
#define MARGIN 0.75f

#define ARS    144            // A(vector) smem row stride bytes (72 bf16)
#define DRS    1040           // dist smem row stride bytes (512 bf16 + 8 pad)

// ---- smem layout (bytes) ---------------------------------------------------
#define SA      0             // bf16 vectors [128][72]          18432
#define SDIST   18432         // bf16 dists [128][520]          133120  (also cb staging)
#define SCN     151552        // fp32 ||c||^2 [512]               2048
#define SVN     153600        // fp32 ||v||^2 [128]                512
#define SMIN    154112        // u32 per-row approx-min key        512
#define SKEY    154624        // ull[128] final keys              1024
#define SRED    155648        // float[512]                       2048
#define SMEM_BYTES 157696

__device__ float          g_cbf[512 * 64];   // fp32 [s][d]
__device__ __nv_bfloat16  g_cbh[512 * 64];   // bf16 [s][d]
__device__ float          g_cn[512];
__device__ float          g_part[NBLK];

#define MMA16816(c0, c1, c2, c3, a0, a1, a2, a3, b0, b1) \
    asm volatile("mma.sync.aligned.m16n8k16.row.col.f32.bf16.bf16.f32 " \
        "{%0,%1,%2,%3}, {%4,%5,%6,%7}, {%8,%9}, {%0,%1,%2,%3};" \
        : "+f"(c0), "+f"(c1), "+f"(c2), "+f"(c3) \
        : "r"(a0), "r"(a1), "r"(a2), "r"(a3), "r"(b0), "r"(b1))

__device__ __forceinline__ uint32_t enc32(float f) {
    uint32_t u = __float_as_uint(f);
    return (u & 0x80000000u) ? ~u : (u | 0x80000000u);
}
__device__ __forceinline__ float dec32(uint32_t m) {
    uint32_t u = (m & 0x80000000u) ? (m & 0x7FFFFFFFu) : ~m;
    return __uint_as_float(u);
}

// ---------------------------------------------------------------------------
// Init: codebook (double trig; identical math to the passing R1/R2 kernels)
// ---------------------------------------------------------------------------
__global__ void vq_init() {
    __shared__ float red[64];
    const int s = blockIdx.x;
    const int d = threadIdx.x;
    const int j = d & 31;

    double expn = -((double)(2 * j) / 64.0);
    float  il   = (float)pow(100000.0, expn);
    float  pre  = __fmul_rn((float)s, il);
    float  e    = (d < 32) ? (float)sin((double)pre) : (float)cos((double)pre);

    red[d] = __fmul_rn(e, e);
    __syncthreads();
    for (int o = 32; o > 0; o >>= 1) {
        if (d < o) red[d] = __fadd_rn(red[d], red[d + o]);
        __syncthreads();
    }
    float m = __fadd_rn(__fmul_rn(red[0], (1.0f / 64.0f)), 1e-6f);
    __syncthreads();
    float r = (float)(1.0 / sqrt((double)m));
    float c = __fmul_rn(__fmul_rn(e, r), 0.35355339059327373f);

    g_cbf[s * 64 + d] = c;
    g_cbh[s * 64 + d] = __float2bfloat16(c);

    red[d] = __fmul_rn(c, c);
    __syncthreads();
    for (int o = 32; o > 0; o >>= 1) {
        if (d < o) red[d] = __fadd_rn(red[d], red[d + o]);
        __syncthreads();
    }
    if (d == 0) g_cn[s] = red[0];
}

// ---------------------------------------------------------------------------
__global__ void __launch_bounds__(NTHR, 1) vq_main(const float* __restrict__ vecs,
                                                   const float* __restrict__ mask,
                                                   float* __restrict__ out) {
    extern __shared__ unsigned char smem[];
    float*    scn   = (float*)(smem + SCN);
    float*    svn   = (float*)(smem + SVN);
    uint32_t* smin  = (uint32_t*)(smem + SMIN);
    ull*      skey  = (ull*)(smem + SKEY);
    float*    sred  = (float*)(smem + SRED);

    const int t  = threadIdx.x;
    const int w  = t >> 5;         // warp 0..15
    const int ln = t & 31;
    const int g  = ln >> 2;        // fragment group 0..7
    const int tq = ln & 3;         // thread-in-group 0..3

    // ---- stage bf16 codebook into SDIST region; copy cn ----
    {
        uint4* dst = (uint4*)(smem + SDIST);
        const uint4* src = (const uint4*)g_cbh;          // 4096 x 16B
        for (int i = t; i < 4096; i += NTHR) dst[i] = src[i];
        for (int i = t; i < NCODE; i += NTHR) scn[i] = g_cn[i];
    }
    __syncthreads();

    // ---- build permanent A (codebook) fragments: warp w owns codes w*32..w*32+31
    // a[s2][kt][0]=(code cb+g, k=kt*16+2tq,+1)  [1]=+8 codes  [2]=k+8  [3]=both
    uint32_t afr[2][4][4];
#pragma unroll
    for (int s2 = 0; s2 < 2; s2++) {
        const int cb = w * 32 + s2 * 16;
#pragma unroll
        for (int kt = 0; kt < 4; kt++) {
            const unsigned char* base = smem + SDIST;
            afr[s2][kt][0] = *(const uint32_t*)(base + (cb + g)     * 128 + kt * 32 + tq * 4);
            afr[s2][kt][1] = *(const uint32_t*)(base + (cb + g + 8) * 128 + kt * 32 + tq * 4);
            afr[s2][kt][2] = *(const uint32_t*)(base + (cb + g)     * 128 + kt * 32 + tq * 4 + 16);
            afr[s2][kt][3] = *(const uint32_t*)(base + (cb + g + 8) * 128 + kt * 32 + tq * 4 + 16);
        }
    }
    __syncthreads();

    float lacc = 0.f;

    for (int tile = blockIdx.x; tile < NTILE; tile += NBLK) {
        const int vbase = tile * 128;
        const int r = t >> 2, q = t & 3;

        // ---- load vectors: fp32 -> vn + bf16 smem [row][72] ----
        {
            const float4* vp = (const float4*)(vecs + ((size_t)(vbase + r)) * 64 + q * 16);
            float4 x0 = vp[0], x1 = vp[1], x2 = vp[2], x3 = vp[3];
            float p = 0.f;
            p = __fadd_rn(p, __fmul_rn(x0.x, x0.x)); p = __fadd_rn(p, __fmul_rn(x0.y, x0.y));
            p = __fadd_rn(p, __fmul_rn(x0.z, x0.z)); p = __fadd_rn(p, __fmul_rn(x0.w, x0.w));
            p = __fadd_rn(p, __fmul_rn(x1.x, x1.x)); p = __fadd_rn(p, __fmul_rn(x1.y, x1.y));
            p = __fadd_rn(p, __fmul_rn(x1.z, x1.z)); p = __fadd_rn(p, __fmul_rn(x1.w, x1.w));
            p = __fadd_rn(p, __fmul_rn(x2.x, x2.x)); p = __fadd_rn(p, __fmul_rn(x2.y, x2.y));
            p = __fadd_rn(p, __fmul_rn(x2.z, x2.z)); p = __fadd_rn(p, __fmul_rn(x2.w, x2.w));
            p = __fadd_rn(p, __fmul_rn(x3.x, x3.x)); p = __fadd_rn(p, __fmul_rn(x3.y, x3.y));
            p = __fadd_rn(p, __fmul_rn(x3.z, x3.z)); p = __fadd_rn(p, __fmul_rn(x3.w, x3.w));
            float s1 = __fadd_rn(p,  __shfl_xor_sync(0xFFFFFFFFu, p, 1));
            float s2 = __fadd_rn(s1, __shfl_xor_sync(0xFFFFFFFFu, s1, 2));
            if (q == 0) svn[r] = s2;

            __nv_bfloat162 h0 = __float22bfloat162_rn(make_float2(x0.x, x0.y));
            __nv_bfloat162 h1 = __float22bfloat162_rn(make_float2(x0.z, x0.w));
            __nv_bfloat162 h2 = __float22bfloat162_rn(make_float2(x1.x, x1.y));
            __nv_bfloat162 h3 = __float22bfloat162_rn(make_float2(x1.z, x1.w));
            __nv_bfloat162 h4 = __float22bfloat162_rn(make_float2(x2.x, x2.y));
            __nv_bfloat162 h5 = __float22bfloat162_rn(make_float2(x2.z, x2.w));
            __nv_bfloat162 h6 = __float22bfloat162_rn(make_float2(x3.x, x3.y));
            __nv_bfloat162 h7 = __float22bfloat162_rn(make_float2(x3.z, x3.w));
            uint4 v0, v1;
            v0.x = *(uint32_t*)&h0; v0.y = *(uint32_t*)&h1;
            v0.z = *(uint32_t*)&h2; v0.w = *(uint32_t*)&h3;
            v1.x = *(uint32_t*)&h4; v1.y = *(uint32_t*)&h5;
            v1.z = *(uint32_t*)&h6; v1.w = *(uint32_t*)&h7;
            *(uint4*)(smem + SA + r * ARS + q * 32)      = v0;
            *(uint4*)(smem + SA + r * ARS + q * 32 + 16) = v1;
        }
        if (t < 128) { smin[t] = 0xFFFFFFFFu; skey[t] = ~0ull; }
        __syncthreads();

        // ---- MMA phase: per warp, 16 row-groups x 2 code-slabs ----
#pragma unroll 1
        for (int rg = 0; rg < 16; rg++) {
            // B (vector) fragments: b[kt][0]=(k=kt*16+2tq,+1, row rg*8+g) b[kt][1]=k+8
            uint32_t bfr[4][2];
#pragma unroll
            for (int kt = 0; kt < 4; kt++) {
                const unsigned char* ba = smem + SA + (rg * 8 + g) * ARS + kt * 32 + tq * 4;
                bfr[kt][0] = *(const uint32_t*)(ba);
                bfr[kt][1] = *(const uint32_t*)(ba + 16);
            }
            const int row0 = rg * 8 + tq * 2;
            const float vn0 = svn[row0], vn1 = svn[row0 + 1];
#pragma unroll
            for (int s2 = 0; s2 < 2; s2++) {
                float c0 = 0.f, c1 = 0.f, c2 = 0.f, c3 = 0.f;
#pragma unroll
                for (int kt = 0; kt < 4; kt++)
                    MMA16816(c0, c1, c2, c3,
                             afr[s2][kt][0], afr[s2][kt][1], afr[s2][kt][2], afr[s2][kt][3],
                             bfr[kt][0], bfr[kt][1]);
                // c0:(code0,row0) c1:(code0,row0+1) c2:(code0+8,row0) c3:(code0+8,row0+1)
                const int code0 = w * 32 + s2 * 16 + g;
                const float cna = scn[code0], cnb = scn[code0 + 8];
                float d00 = __fadd_rn(fmaf(-2.f, c0, vn0), cna);
                float d01 = __fadd_rn(fmaf(-2.f, c1, vn1), cna);
                float d10 = __fadd_rn(fmaf(-2.f, c2, vn0), cnb);
                float d11 = __fadd_rn(fmaf(-2.f, c3, vn1), cnb);
                __nv_bfloat16* dd = (__nv_bfloat16*)(smem + SDIST);
                dd[(row0)     * (DRS / 2) + code0]     = __float2bfloat16(d00);
                dd[(row0 + 1) * (DRS / 2) + code0]     = __float2bfloat16(d01);
                dd[(row0)     * (DRS / 2) + code0 + 8] = __float2bfloat16(d10);
                dd[(row0 + 1) * (DRS / 2) + code0 + 8] = __float2bfloat16(d11);
            }
        }
        __syncthreads();

        // ---- pass 1: per-row approx min over stored bf16 dists ----
        {
            const int row = t >> 2, seg = t & 3;
            const uint4* base = (const uint4*)(smem + SDIST + row * DRS + seg * 256);
            float mn = 3.4e38f;
#pragma unroll
            for (int i = 0; i < 16; i++) {
                uint4 wv = base[i];
                uint32_t a = wv.x, b = wv.y, c = wv.z, d = wv.w;
                mn = fminf(mn, __uint_as_float(a << 16));
                mn = fminf(mn, __uint_as_float(a & 0xFFFF0000u));
                mn = fminf(mn, __uint_as_float(b << 16));
                mn = fminf(mn, __uint_as_float(b & 0xFFFF0000u));
                mn = fminf(mn, __uint_as_float(c << 16));
                mn = fminf(mn, __uint_as_float(c & 0xFFFF0000u));
                mn = fminf(mn, __uint_as_float(d << 16));
                mn = fminf(mn, __uint_as_float(d & 0xFFFF0000u));
            }
            atomicMin(&smin[row], enc32(mn));
        }
        __syncthreads();

        // ---- pass 2: threshold scan + exact fp32 refine ----
        {
            const int row = t >> 2, seg = t & 3;
            const float thr = dec32(smin[row]) + MARGIN;
            const uint4* base = (const uint4*)(smem + SDIST + row * DRS + seg * 256);
#pragma unroll 1
            for (int i = 0; i < 16; i++) {
                uint4 wv = base[i];
                uint32_t ws[4] = {wv.x, wv.y, wv.z, wv.w};
#pragma unroll
                for (int j = 0; j < 4; j++) {
                    float flo = __uint_as_float(ws[j] << 16);
                    float fhi = __uint_as_float(ws[j] & 0xFFFF0000u);
#pragma unroll
                    for (int e = 0; e < 2; e++) {
                        float fv = e ? fhi : flo;
                        if (fv < thr) {
                            int code = seg * 128 + i * 8 + j * 2 + e;
                            const float4* vp = (const float4*)(vecs + ((size_t)(vbase + row)) * 64);
                            const float4* cp = (const float4*)(g_cbf + (size_t)code * 64);
                            float dot = 0.f;
#pragma unroll
                            for (int kk = 0; kk < 16; kk++) {
                                float4 a = vp[kk], b = cp[kk];
                                dot = fmaf(a.x, b.x, dot);
                                dot = fmaf(a.y, b.y, dot);
                                dot = fmaf(a.z, b.z, dot);
                                dot = fmaf(a.w, b.w, dot);
                            }
                            float dist = __fadd_rn(fmaf(-2.f, dot, svn[row]), scn[code]);
                            ull key = ((ull)enc32(dist) << 9) | (uint32_t)code;
                            atomicMin(&skey[row], key);
                        }
                    }
                }
            }
        }
        __syncthreads();

        // ---- outputs ----
        if (t < 128) {
            ull key = skey[t];
            int s = (int)(key & 511);
            float dist = dec32((uint32_t)(key >> 9));
            float er = fmaxf(dist, 0.f);
            int v = vbase + t;
            out[ZOFF + v] = (float)s;
            out[EOFF + v] = er;
            lacc = __fadd_rn(lacc, __fmul_rn(mask[v], er));
        }
        {
            int s = (int)(skey[r] & 511);
            const float4* cp = (const float4*)(g_cbf + (size_t)s * 64 + q * 16);
            float4* dst = (float4*)(out + ((size_t)(vbase + r)) * 64 + q * 16);
            dst[0] = cp[0]; dst[1] = cp[1]; dst[2] = cp[2]; dst[3] = cp[3];
        }
        __syncthreads();
    }

    // ---- l_commit block partial ----
    sred[t] = lacc;
    __syncthreads();
    for (int o = NTHR / 2; o > 0; o >>= 1) {
        if (t < o) sred[t] = __fadd_rn(sred[t], sred[t + o]);
        __syncthreads();
    }
    if (t == 0) g_part[blockIdx.x] = sred[0];
}

// ---------------------------------------------------------------------------
__global__ void vq_final(float* __restrict__ out) {
    __shared__ float s[256];
    int t = threadIdx.x;
    s[t] = (t < NBLK) ? g_part[t] : 0.f;
    __syncthreads();
    for (int o = 128; o > 0; o >>= 1) {
        if (t < o) s[t] = __fadd_rn(s[t], s[t + o]);
        __syncthreads();
    }
    if (t == 0) out[LOFF] = __fmul_rn(s[0], (1.0f / 131072.0f));
}

// ---------------------------------------------------------------------------
extern "C" void kernel_launch(void* const* d_in, const int* in_sizes, int n_in,
                              void* d_out, int out_size) {
    (void)in_sizes; (void)n_in; (void)out_size;
    const float* vecs = (const float*)d_in[0];
    const float* mask = (const float*)d_in[1];
    float* out = (float*)d_out;

    cudaFuncSetAttribute(vq_main, cudaFuncAttributeMaxDynamicSharedMemorySize, SMEM_BYTES);

    vq_init<<<NCODE, 64>>>();
    vq_main<<<NBLK, NTHR, SMEM_BYTES>>>(vecs, mask, out);
    vq_final<<<1, 256>>>(out);
}